// round 2
// baseline (speedup 1.0000x reference)
#include <cuda_runtime.h>
#include <math.h>

#define BATCH 8192
#define NCVS  4096
#define FEAT  128
#define KNN   15

// ---------------- static scratch (no runtime allocation allowed) ----------------
__device__ float  g_d2[(size_t)BATCH * NCVS];   // 128 MB distance matrix
__device__ int    g_cce[(size_t)NCVS * NCVS];   // 64 MB co-encounter counts
__device__ int    g_visits[NCVS];
__device__ int    g_knn[BATCH * KNN];
__device__ float  g_xx[BATCH];
__device__ float  g_cc[NCVS];
__device__ double g_loss;

// ---------------- f32x2 packed-FMA helpers (sm_103a) ----------------
__device__ __forceinline__ unsigned long long f32x2_dup(float a) {
    unsigned long long r;
    asm("mov.b64 %0, {%1, %2};" : "=l"(r) : "f"(a), "f"(a));
    return r;
}
__device__ __forceinline__ void fma_f32x2(unsigned long long &d,
                                          unsigned long long a,
                                          unsigned long long b) {
    asm("fma.rn.f32x2 %0, %1, %2, %0;" : "+l"(d) : "l"(a), "l"(b));
}
__device__ __forceinline__ float2 f32x2_unpack(unsigned long long v) {
    float2 r;
    asm("mov.b64 {%0, %1}, %2;" : "=f"(r.x), "=f"(r.y) : "l"(v));
    return r;
}

// ---------------- K0: zero scratch ----------------
__global__ void zero_kernel() {
    size_t i  = (size_t)blockIdx.x * blockDim.x + threadIdx.x;
    size_t n4 = (size_t)NCVS * NCVS / 4;
    int4 z = make_int4(0, 0, 0, 0);
    for (size_t idx = i; idx < n4; idx += (size_t)gridDim.x * blockDim.x)
        ((int4*)g_cce)[idx] = z;
    if (i < NCVS) g_visits[i] = 0;
    if (i == 0)   g_loss = 0.0;
}

// ---------------- K1: row squared norms (one warp per row) ----------------
__global__ void norms_kernel(const float* __restrict__ X, const float* __restrict__ C) {
    int warp = (blockIdx.x * blockDim.x + threadIdx.x) >> 5;
    int lane = threadIdx.x & 31;
    if (warp < BATCH) {
        const float* r = X + (size_t)warp * FEAT;
        float s = 0.f;
        #pragma unroll
        for (int i = 0; i < 4; i++) { float v = r[lane + 32 * i]; s += v * v; }
        #pragma unroll
        for (int o = 16; o; o >>= 1) s += __shfl_down_sync(0xffffffffu, s, o);
        if (lane == 0) g_xx[warp] = s;
    } else if (warp < BATCH + NCVS) {
        int rr = warp - BATCH;
        const float* r = C + (size_t)rr * FEAT;
        float s = 0.f;
        #pragma unroll
        for (int i = 0; i < 4; i++) { float v = r[lane + 32 * i]; s += v * v; }
        #pragma unroll
        for (int o = 16; o; o >>= 1) s += __shfl_down_sync(0xffffffffu, s, o);
        if (lane == 0) g_cc[rr] = s;
    }
}

// ---------------- K2: distance GEMM (128x128 tile, f32x2 packed FMA) ----------------
__global__ __launch_bounds__(256, 2) void gemm_kernel(const float* __restrict__ X,
                                                      const float* __restrict__ C) {
    __shared__ float As[16][128];   // [k][m] transposed x tile
    __shared__ float Bs[16][128];   // [k][n] transposed cvs tile

    const int bm  = blockIdx.y * 128;
    const int bn  = blockIdx.x * 128;
    const int tid = threadIdx.x;
    const int tx  = tid & 15;   // n sub-tile
    const int ty  = tid >> 4;   // m sub-tile

    unsigned long long acc[8][4];
    #pragma unroll
    for (int i = 0; i < 8; i++)
        #pragma unroll
        for (int j = 0; j < 4; j++) acc[i][j] = 0ull;

    const int lr  = tid >> 1;           // load row within tile 0..127
    const int kk0 = (tid & 1) * 8;      // k offset base {0,8}
    const float* Xrow = X + (size_t)(bm + lr) * FEAT;
    const float* Crow = C + (size_t)(bn + lr) * FEAT;

    for (int kc = 0; kc < FEAT; kc += 16) {
        float4 a0 = *(const float4*)(Xrow + kc + kk0);
        float4 a1 = *(const float4*)(Xrow + kc + kk0 + 4);
        float4 b0 = *(const float4*)(Crow + kc + kk0);
        float4 b1 = *(const float4*)(Crow + kc + kk0 + 4);
        As[kk0 + 0][lr] = a0.x; As[kk0 + 1][lr] = a0.y;
        As[kk0 + 2][lr] = a0.z; As[kk0 + 3][lr] = a0.w;
        As[kk0 + 4][lr] = a1.x; As[kk0 + 5][lr] = a1.y;
        As[kk0 + 6][lr] = a1.z; As[kk0 + 7][lr] = a1.w;
        Bs[kk0 + 0][lr] = b0.x; Bs[kk0 + 1][lr] = b0.y;
        Bs[kk0 + 2][lr] = b0.z; Bs[kk0 + 3][lr] = b0.w;
        Bs[kk0 + 4][lr] = b1.x; Bs[kk0 + 5][lr] = b1.y;
        Bs[kk0 + 6][lr] = b1.z; Bs[kk0 + 7][lr] = b1.w;
        __syncthreads();

        #pragma unroll
        for (int k = 0; k < 16; k++) {
            ulonglong2 bb0 = *(const ulonglong2*)&Bs[k][tx * 8];
            ulonglong2 bb1 = *(const ulonglong2*)&Bs[k][tx * 8 + 4];
            float4 av0 = *(const float4*)&As[k][ty * 8];
            float4 av1 = *(const float4*)&As[k][ty * 8 + 4];
            float a[8] = {av0.x, av0.y, av0.z, av0.w, av1.x, av1.y, av1.z, av1.w};
            unsigned long long bl[4] = {bb0.x, bb0.y, bb1.x, bb1.y};
            #pragma unroll
            for (int m = 0; m < 8; m++) {
                unsigned long long ad = f32x2_dup(a[m]);
                #pragma unroll
                for (int n = 0; n < 4; n++) fma_f32x2(acc[m][n], ad, bl[n]);
            }
        }
        __syncthreads();
    }

    // epilogue: d2 = xx + cc - 2*dot, clamp >= 0
    #pragma unroll
    for (int m = 0; m < 8; m++) {
        int gm = bm + ty * 8 + m;
        float xxv = g_xx[gm];
        float out[8];
        #pragma unroll
        for (int n = 0; n < 4; n++) {
            float2 p = f32x2_unpack(acc[m][n]);
            int gn = bn + tx * 8 + n * 2;
            out[n * 2]     = fmaxf(xxv + g_cc[gn]     - 2.0f * p.x, 0.0f);
            out[n * 2 + 1] = fmaxf(xxv + g_cc[gn + 1] - 2.0f * p.y, 0.0f);
        }
        float* dst = g_d2 + (size_t)gm * NCVS + bn + tx * 8;
        *(float4*)dst       = make_float4(out[0], out[1], out[2], out[3]);
        *(float4*)(dst + 4) = make_float4(out[4], out[5], out[6], out[7]);
    }
}

// ---------------- K3: top-15 per row (register candidates + lazy rescan) ----------------
__global__ void topk_kernel() {
    __shared__ unsigned long long wmin[8];
    int row  = blockIdx.x;
    int tid  = threadIdx.x;
    int lane = tid & 31, wid = tid >> 5;
    const float* drow = g_d2 + (size_t)row * NCVS;

    float v[16];
    #pragma unroll
    for (int jj = 0; jj < 16; jj++) v[jj] = drow[tid + (jj << 8)];

    unsigned long long best = ~0ull;
    #pragma unroll
    for (int jj = 0; jj < 16; jj++) {
        unsigned long long key =
            ((unsigned long long)__float_as_uint(v[jj]) << 32) | (unsigned)(tid + (jj << 8));
        best = (key < best) ? key : best;
    }

    for (int it = 0; it < KNN; it++) {
        unsigned long long t = best;
        #pragma unroll
        for (int o = 16; o; o >>= 1) {
            unsigned long long other = __shfl_down_sync(0xffffffffu, t, o);
            t = (other < t) ? other : t;
        }
        if (lane == 0) wmin[wid] = t;
        __syncthreads();
        unsigned long long g = wmin[0];
        #pragma unroll
        for (int w = 1; w < 8; w++) g = (wmin[w] < g) ? wmin[w] : g;
        int jsel = (int)(g & 0xffffffffu);
        if (tid == 0) g_knn[row * KNN + it] = jsel;
        if ((jsel & 255) == tid) {
            int jj_sel = jsel >> 8;
            #pragma unroll
            for (int jj = 0; jj < 16; jj++)
                if (jj == jj_sel) v[jj] = __int_as_float(0x7f800000);  // +inf
            best = ~0ull;
            #pragma unroll
            for (int jj = 0; jj < 16; jj++) {
                unsigned long long key =
                    ((unsigned long long)__float_as_uint(v[jj]) << 32) | (unsigned)(tid + (jj << 8));
                best = (key < best) ? key : best;
            }
        }
        __syncthreads();
    }
}

// ---------------- K4: scatter visits / cce ----------------
__global__ void scatter_kernel() {
    int b = blockIdx.x * blockDim.x + threadIdx.x;
    if (b >= BATCH) return;
    int closest = g_knn[b * KNN];
    atomicAdd(&g_visits[closest], 1);
    #pragma unroll
    for (int k = 0; k < KNN; k++)
        atomicAdd(&g_cce[(size_t)closest * NCVS + g_knn[b * KNN + k]], 1);
}

// ---------------- K5: per-sample loss ----------------
// Keep semantics: reference computes edges_new = (0.9f)^enc in float32 and
// compares against E_MIN = double(0.9^10) downcast to f32 (0.34867844358f).
// Since 0.9f < 0.9 exactly, (0.9f)^10 ~= 0.34867835 < E_MIN_f32, so enc == 10
// is ZEROED by the reference. Effective keep condition: enc <= 9.
__global__ void loss_kernel(const float* __restrict__ X, const float* __restrict__ C,
                            const float* __restrict__ edges, const float* __restrict__ conn,
                            const int* __restrict__ labels) {
    __shared__ float s_dp[4], s_se[4], s_sed[4];
    int b    = blockIdx.x;
    int tid  = threadIdx.x;
    int lane = tid & 31, wid = tid >> 5;
    int lab  = labels[b];

    const float* xr = X + (size_t)b   * FEAT;
    const float* cr = C + (size_t)lab * FEAT;
    float dlt = xr[tid] - cr[tid];
    float dp  = dlt * dlt;                       // exact d_pos term

    float vis = (float)g_visits[lab];
    const int*   ccer = g_cce + (size_t)lab * NCVS;
    const float* er   = edges + (size_t)lab * NCVS;
    const float* cor  = conn  + (size_t)lab * NCVS;
    const float* d2r  = g_d2  + (size_t)b   * NCVS;

    float se = 0.f, sed = 0.f;
    for (int j = tid; j < NCVS; j += 128) {
        int   c  = ccer[j];
        float ev = er[j];
        if (c > 0 || ev > 0.f) {
            float base = fmaxf(ev, (c > 0) ? 1.0f : 0.0f);
            float enc  = fmaxf(vis - (float)c, 0.0f);
            bool keep;
            if (base >= 1.0f) keep = (enc < 9.5f);   // see comment above: enc<=9 survives
            else {
                // generic fractional-edge path (unused for identity edges):
                float en = base * __powf(0.89999997615814209f, enc);
                keep = !(en < 0.34867844358f);
            }
            if (keep && cor[j] < 1.0f) {
                float dd = d2r[j];
                if (dd > 0.f) {
                    float ex = expf(-0.001f * dd);
                    se  += ex;
                    sed += ex * dd;
                }
            }
        }
    }

    #pragma unroll
    for (int o = 16; o; o >>= 1) {
        dp  += __shfl_down_sync(0xffffffffu, dp,  o);
        se  += __shfl_down_sync(0xffffffffu, se,  o);
        sed += __shfl_down_sync(0xffffffffu, sed, o);
    }
    if (lane == 0) { s_dp[wid] = dp; s_se[wid] = se; s_sed[wid] = sed; }
    __syncthreads();
    if (tid == 0) {
        dp  = s_dp[0]  + s_dp[1]  + s_dp[2]  + s_dp[3];
        se  = s_se[0]  + s_se[1]  + s_se[2]  + s_se[3];
        sed = s_sed[0] + s_sed[1] + s_sed[2] + s_sed[3];
        float wsum = (se > 0.f) ? (sed / se) : 0.f;   // nan -> 0 branch
        float mu = dp - wsum;
        if (mu > 0.f) atomicAdd(&g_loss, (double)mu);
    }
}

// ---------------- K6: finalize ----------------
__global__ void finalize_kernel(float* out) {
    if (threadIdx.x == 0) out[0] = (float)(g_loss * (1.0 / (double)BATCH));
}

// ---------------- launch ----------------
extern "C" void kernel_launch(void* const* d_in, const int* in_sizes, int n_in,
                              void* d_out, int out_size) {
    const float* x      = (const float*)d_in[0];
    const float* cvs    = (const float*)d_in[1];
    const float* edges  = (const float*)d_in[2];
    const float* conn   = (const float*)d_in[3];
    const int*   labels = (const int*)d_in[4];
    float* out = (float*)d_out;

    zero_kernel<<<4096, 256>>>();
    norms_kernel<<<(BATCH + NCVS) / 8, 256>>>(x, cvs);
    gemm_kernel<<<dim3(NCVS / 128, BATCH / 128), 256>>>(x, cvs);
    topk_kernel<<<BATCH, 256>>>();
    scatter_kernel<<<BATCH / 256, 256>>>();
    loss_kernel<<<BATCH, 128>>>(x, cvs, edges, conn, labels);
    finalize_kernel<<<1, 32>>>(out);
}

// round 3
// speedup vs baseline: 1.1160x; 1.1160x over previous
#include <cuda_runtime.h>
#include <math.h>

#define BATCH 8192
#define NCVS  4096
#define FEAT  128
#define KNN   15

// ---------------- static scratch (no runtime allocation allowed) ----------------
__device__ float  g_d2[(size_t)BATCH * NCVS];    // 128 MB distance matrix
__device__ int    g_cce[(size_t)NCVS * NCVS];    // 64 MB co-encounter counts (self-cleaning)
__device__ int    g_nlist[(size_t)NCVS * NCVS];  // 64 MB per-label neighbor lists
__device__ int    g_ncnt[NCVS];
__device__ int    g_visits[NCVS];                // self-cleaning
__device__ int    g_knn[BATCH * KNN];
__device__ float  g_xx[BATCH];
__device__ float  g_cc[NCVS];
__device__ double g_loss;                        // self-cleaning

// ---------------- f32x2 packed-FMA helpers (sm_103a) ----------------
__device__ __forceinline__ unsigned long long f32x2_dup(float a) {
    unsigned long long r;
    asm("mov.b64 %0, {%1, %2};" : "=l"(r) : "f"(a), "f"(a));
    return r;
}
__device__ __forceinline__ void fma_f32x2(unsigned long long &d,
                                          unsigned long long a,
                                          unsigned long long b) {
    asm("fma.rn.f32x2 %0, %1, %2, %0;" : "+l"(d) : "l"(a), "l"(b));
}
__device__ __forceinline__ float2 f32x2_unpack(unsigned long long v) {
    float2 r;
    asm("mov.b64 {%0, %1}, %2;" : "=f"(r.x), "=f"(r.y) : "l"(v));
    return r;
}

// ---------------- K1: row squared norms (one warp per row) ----------------
__global__ void norms_kernel(const float* __restrict__ X, const float* __restrict__ C) {
    int warp = (blockIdx.x * blockDim.x + threadIdx.x) >> 5;
    int lane = threadIdx.x & 31;
    if (warp < BATCH) {
        const float* r = X + (size_t)warp * FEAT;
        float s = 0.f;
        #pragma unroll
        for (int i = 0; i < 4; i++) { float v = r[lane + 32 * i]; s += v * v; }
        #pragma unroll
        for (int o = 16; o; o >>= 1) s += __shfl_down_sync(0xffffffffu, s, o);
        if (lane == 0) g_xx[warp] = s;
    } else if (warp < BATCH + NCVS) {
        int rr = warp - BATCH;
        const float* r = C + (size_t)rr * FEAT;
        float s = 0.f;
        #pragma unroll
        for (int i = 0; i < 4; i++) { float v = r[lane + 32 * i]; s += v * v; }
        #pragma unroll
        for (int o = 16; o; o >>= 1) s += __shfl_down_sync(0xffffffffu, s, o);
        if (lane == 0) g_cc[rr] = s;
    }
}

// ---------------- K2: distance GEMM (128x128 tile, f32x2 packed FMA) ----------------
__global__ __launch_bounds__(256, 2) void gemm_kernel(const float* __restrict__ X,
                                                      const float* __restrict__ C) {
    __shared__ float As[16][128];   // [k][m]
    __shared__ float Bs[16][128];   // [k][n]

    const int bm  = blockIdx.y * 128;
    const int bn  = blockIdx.x * 128;
    const int tid = threadIdx.x;
    const int tx  = tid & 15;
    const int ty  = tid >> 4;

    unsigned long long acc[8][4];
    #pragma unroll
    for (int i = 0; i < 8; i++)
        #pragma unroll
        for (int j = 0; j < 4; j++) acc[i][j] = 0ull;

    const int lr  = tid >> 1;
    const int kk0 = (tid & 1) * 8;
    const float* Xrow = X + (size_t)(bm + lr) * FEAT;
    const float* Crow = C + (size_t)(bn + lr) * FEAT;

    // software pipeline: preload first chunk
    float4 a0 = *(const float4*)(Xrow + kk0);
    float4 a1 = *(const float4*)(Xrow + kk0 + 4);
    float4 b0 = *(const float4*)(Crow + kk0);
    float4 b1 = *(const float4*)(Crow + kk0 + 4);

    for (int kc = 0; kc < FEAT; kc += 16) {
        As[kk0 + 0][lr] = a0.x; As[kk0 + 1][lr] = a0.y;
        As[kk0 + 2][lr] = a0.z; As[kk0 + 3][lr] = a0.w;
        As[kk0 + 4][lr] = a1.x; As[kk0 + 5][lr] = a1.y;
        As[kk0 + 6][lr] = a1.z; As[kk0 + 7][lr] = a1.w;
        Bs[kk0 + 0][lr] = b0.x; Bs[kk0 + 1][lr] = b0.y;
        Bs[kk0 + 2][lr] = b0.z; Bs[kk0 + 3][lr] = b0.w;
        Bs[kk0 + 4][lr] = b1.x; Bs[kk0 + 5][lr] = b1.y;
        Bs[kk0 + 6][lr] = b1.z; Bs[kk0 + 7][lr] = b1.w;
        __syncthreads();

        if (kc + 16 < FEAT) {   // prefetch next chunk during compute
            a0 = *(const float4*)(Xrow + kc + 16 + kk0);
            a1 = *(const float4*)(Xrow + kc + 16 + kk0 + 4);
            b0 = *(const float4*)(Crow + kc + 16 + kk0);
            b1 = *(const float4*)(Crow + kc + 16 + kk0 + 4);
        }

        #pragma unroll
        for (int k = 0; k < 16; k++) {
            ulonglong2 bb0 = *(const ulonglong2*)&Bs[k][tx * 8];
            ulonglong2 bb1 = *(const ulonglong2*)&Bs[k][tx * 8 + 4];
            float4 av0 = *(const float4*)&As[k][ty * 8];
            float4 av1 = *(const float4*)&As[k][ty * 8 + 4];
            float a[8] = {av0.x, av0.y, av0.z, av0.w, av1.x, av1.y, av1.z, av1.w};
            unsigned long long bl[4] = {bb0.x, bb0.y, bb1.x, bb1.y};
            #pragma unroll
            for (int m = 0; m < 8; m++) {
                unsigned long long ad = f32x2_dup(a[m]);
                #pragma unroll
                for (int n = 0; n < 4; n++) fma_f32x2(acc[m][n], ad, bl[n]);
            }
        }
        __syncthreads();
    }

    #pragma unroll
    for (int m = 0; m < 8; m++) {
        int gm = bm + ty * 8 + m;
        float xxv = g_xx[gm];
        float out[8];
        #pragma unroll
        for (int n = 0; n < 4; n++) {
            float2 p = f32x2_unpack(acc[m][n]);
            int gn = bn + tx * 8 + n * 2;
            out[n * 2]     = fmaxf(xxv + g_cc[gn]     - 2.0f * p.x, 0.0f);
            out[n * 2 + 1] = fmaxf(xxv + g_cc[gn + 1] - 2.0f * p.y, 0.0f);
        }
        float* dst = g_d2 + (size_t)gm * NCVS + bn + tx * 8;
        *(float4*)dst       = make_float4(out[0], out[1], out[2], out[3]);
        *(float4*)(dst + 4) = make_float4(out[4], out[5], out[6], out[7]);
    }
}

// ---------------- K3: top-15 per row, warp-autonomous 2-stage + fused scatter --------
// d2 >= 0 so float bits are order-preserving as uint32. REDUX-based selection.
__global__ void topk_kernel() {
    __shared__ unsigned s_cb[128];   // candidate distance bits (8 warps x 15, padded)
    __shared__ int      s_cj[128];   // candidate j
    __shared__ int      s_knn[KNN];

    const int row  = blockIdx.x;
    const int tid  = threadIdx.x;
    const int lane = tid & 31, w = tid >> 5;
    const float* drow = g_d2 + (size_t)row * NCVS;
    const int wbase = w * 512;

    // ---- stage 1: each warp selects top-15 of its 512 values (no block barriers) ----
    unsigned v[16];
    #pragma unroll
    for (int i = 0; i < 16; i++)
        v[i] = __float_as_uint(drow[wbase + i * 32 + lane]);

    unsigned best = 0xFFFFFFFFu; int argj = 0x7FFFFFFF;
    #pragma unroll
    for (int i = 0; i < 16; i++)
        if (v[i] < best) { best = v[i]; argj = wbase + i * 32 + lane; }

    #pragma unroll 1
    for (int it = 0; it < KNN; it++) {
        unsigned vmin = __reduce_min_sync(0xffffffffu, best);
        unsigned myj  = (best == vmin) ? (unsigned)argj : 0xFFFFFFFFu;
        unsigned jmin = __reduce_min_sync(0xffffffffu, myj);
        if (lane == 0) { s_cb[w * KNN + it] = vmin; s_cj[w * KNN + it] = (int)jmin; }
        if ((int)(jmin & 31) == lane) {   // owner lane removes and rescans
            int i_sel = (int)((jmin - wbase) >> 5);
            v[i_sel] = 0xFFFFFFFFu;
            best = 0xFFFFFFFFu; argj = 0x7FFFFFFF;
            #pragma unroll
            for (int i = 0; i < 16; i++)
                if (v[i] < best) { best = v[i]; argj = wbase + i * 32 + lane; }
        }
    }
    __syncthreads();

    // ---- stage 2: warp 0 merges 120 candidates ----
    if (w == 0) {
        unsigned cb[4]; int cj[4];
        #pragma unroll
        for (int q = 0; q < 4; q++) {
            int idx = q * 32 + lane;
            bool ok = idx < 8 * KNN;
            cb[q] = ok ? s_cb[idx] : 0xFFFFFFFFu;
            cj[q] = ok ? s_cj[idx] : 0x7FFFFFFF;
        }
        unsigned b2 = 0xFFFFFFFFu; int a2 = 0x7FFFFFFF;
        #pragma unroll
        for (int q = 0; q < 4; q++)
            if (cb[q] < b2 || (cb[q] == b2 && cj[q] < a2)) { b2 = cb[q]; a2 = cj[q]; }

        #pragma unroll 1
        for (int it = 0; it < KNN; it++) {
            unsigned vmin = __reduce_min_sync(0xffffffffu, b2);
            unsigned myj  = (b2 == vmin) ? (unsigned)a2 : 0xFFFFFFFFu;
            unsigned jmin = __reduce_min_sync(0xffffffffu, myj);
            if (lane == 0) { s_knn[it] = (int)jmin; g_knn[row * KNN + it] = (int)jmin; }
            // owner: lane holding this (vmin, jmin) entry removes it
            bool own = false;
            #pragma unroll
            for (int q = 0; q < 4; q++)
                if (cj[q] == (int)jmin && cb[q] == vmin) { cb[q] = 0xFFFFFFFFu; own = true; }
            if (own) {
                b2 = 0xFFFFFFFFu; a2 = 0x7FFFFFFF;
                #pragma unroll
                for (int q = 0; q < 4; q++)
                    if (cb[q] < b2 || (cb[q] == b2 && cj[q] < a2)) { b2 = cb[q]; a2 = cj[q]; }
            }
        }
        __syncwarp();
        // ---- fused scatter ----
        int closest = s_knn[0];
        if (lane == 0) atomicAdd(&g_visits[closest], 1);
        if (lane < KNN) atomicAdd(&g_cce[(size_t)closest * NCVS + s_knn[lane]], 1);
    }
}

// ---------------- K4: build per-label neighbor lists (keep mask depends only on lab) --
// Keep semantics: reference computes edges_new = (0.9f)^enc in f32 vs E_MIN =
// f32(double(0.9^10)) = 0.34867844358f; (0.9f)^10 = 0.34867835 < E_MIN, so
// integer-edge rows keep enc <= 9 only.
__global__ void build_kernel(const float* __restrict__ edges, const float* __restrict__ conn) {
    __shared__ int s_scan[256];
    const int lab = blockIdx.x;
    const int tid = threadIdx.x;
    float vis = (float)g_visits[lab];
    const int*   ccer = g_cce + (size_t)lab * NCVS;
    const float* er   = edges + (size_t)lab * NCVS;
    const float* cor  = conn  + (size_t)lab * NCVS;

    unsigned mask = 0; int cnt = 0;
    #pragma unroll
    for (int it = 0; it < 16; it++) {
        int j = tid + (it << 8);
        int c = ccer[j]; float ev = er[j];
        bool keep = false;
        if (c > 0 || ev > 0.f) {
            float base = fmaxf(ev, (c > 0) ? 1.0f : 0.0f);
            float enc  = fmaxf(vis - (float)c, 0.0f);
            if (base >= 1.0f) keep = (enc < 9.5f);
            else {
                float en = base * __powf(0.89999997615814209f, enc);
                keep = !(en < 0.34867844358f);
            }
            keep = keep && (cor[j] < 1.0f);
        }
        if (keep) { mask |= (1u << it); cnt++; }
    }
    s_scan[tid] = cnt;
    __syncthreads();
    for (int off = 1; off < 256; off <<= 1) {
        int vv = (tid >= off) ? s_scan[tid - off] : 0;
        __syncthreads();
        s_scan[tid] += vv;
        __syncthreads();
    }
    int pos = s_scan[tid] - cnt;
    int* dst = g_nlist + (size_t)lab * NCVS;
    #pragma unroll
    for (int it = 0; it < 16; it++)
        if (mask & (1u << it)) dst[pos++] = tid + (it << 8);
    if (tid == 255) g_ncnt[lab] = s_scan[255];
}

// ---------------- K5: per-sample loss over compact neighbor list ----------------
__global__ void loss_kernel(const float* __restrict__ X, const float* __restrict__ C,
                            const int* __restrict__ labels) {
    __shared__ float s_dp[4], s_se[4], s_sed[4];
    const int b    = blockIdx.x;
    const int tid  = threadIdx.x;
    const int lane = tid & 31, wid = tid >> 5;
    const int lab  = labels[b];

    const float* xr = X + (size_t)b   * FEAT;
    const float* cr = C + (size_t)lab * FEAT;
    float dlt = xr[tid] - cr[tid];
    float dp  = dlt * dlt;

    const int  L   = g_ncnt[lab];
    const int* nl  = g_nlist + (size_t)lab * NCVS;
    const float* d2r = g_d2 + (size_t)b * NCVS;

    float se = 0.f, sed = 0.f;
    for (int k = tid; k < L; k += 128) {
        int j = nl[k];
        float dd = d2r[j];
        if (dd > 0.f) {
            float ex = expf(-0.001f * dd);
            se  += ex;
            sed += ex * dd;
        }
    }

    #pragma unroll
    for (int o = 16; o; o >>= 1) {
        dp  += __shfl_down_sync(0xffffffffu, dp,  o);
        se  += __shfl_down_sync(0xffffffffu, se,  o);
        sed += __shfl_down_sync(0xffffffffu, sed, o);
    }
    if (lane == 0) { s_dp[wid] = dp; s_se[wid] = se; s_sed[wid] = sed; }
    __syncthreads();
    if (tid == 0) {
        dp  = s_dp[0]  + s_dp[1]  + s_dp[2]  + s_dp[3];
        se  = s_se[0]  + s_se[1]  + s_se[2]  + s_se[3];
        sed = s_sed[0] + s_sed[1] + s_sed[2] + s_sed[3];
        float wsum = (se > 0.f) ? (sed / se) : 0.f;   // nan -> 0 branch
        float mu = dp - wsum;
        if (mu > 0.f) atomicAdd(&g_loss, (double)mu);
    }
}

// ---------------- K6: finalize ----------------
__global__ void finalize_kernel(float* out) {
    if (threadIdx.x == 0) out[0] = (float)(g_loss * (1.0 / (double)BATCH));
}

// ---------------- K7: undo scatter (self-cleaning state; replaces 64MB zero sweep) ---
__global__ void undo_kernel() {
    int b = blockIdx.x * blockDim.x + threadIdx.x;
    if (b == 0) g_loss = 0.0;
    if (b >= BATCH) return;
    int closest = g_knn[b * KNN];
    atomicSub(&g_visits[closest], 1);
    #pragma unroll
    for (int k = 0; k < KNN; k++)
        atomicSub(&g_cce[(size_t)closest * NCVS + g_knn[b * KNN + k]], 1);
}

// ---------------- launch ----------------
extern "C" void kernel_launch(void* const* d_in, const int* in_sizes, int n_in,
                              void* d_out, int out_size) {
    const float* x      = (const float*)d_in[0];
    const float* cvs    = (const float*)d_in[1];
    const float* edges  = (const float*)d_in[2];
    const float* conn   = (const float*)d_in[3];
    const int*   labels = (const int*)d_in[4];
    float* out = (float*)d_out;

    norms_kernel<<<(BATCH + NCVS) / 8, 256>>>(x, cvs);
    gemm_kernel<<<dim3(NCVS / 128, BATCH / 128), 256>>>(x, cvs);
    topk_kernel<<<BATCH, 256>>>();
    build_kernel<<<NCVS, 256>>>(edges, conn);
    loss_kernel<<<BATCH, 128>>>(x, cvs, labels);
    finalize_kernel<<<1, 32>>>(out);
    undo_kernel<<<BATCH / 256, 256>>>();
}

// round 6
// speedup vs baseline: 1.6402x; 1.4697x over previous
#include <cuda_runtime.h>
#include <cuda_bf16.h>
#include <cstdint>
#include <math.h>

#define BATCH 8192
#define NCVS  4096
#define FEAT  128
#define KNN   15
#define NCAND 24   // rescue candidate count

// ---------------- static scratch ----------------
__device__ float  g_d2[(size_t)BATCH * NCVS];    // approx (bf16-GEMM) distances, f32
__device__ int    g_cce[(size_t)NCVS * NCVS];    // self-cleaning via undo
__device__ int    g_nlist[(size_t)NCVS * NCVS];  // per-label neighbor lists
__device__ int    g_ncnt[NCVS];
__device__ int    g_visits[NCVS];                // self-cleaning
__device__ int    g_knn[BATCH * KNN];
__device__ float  g_xx[BATCH];
__device__ float  g_cc[NCVS];
__device__ double g_loss;                        // self-cleaning
__device__ __nv_bfloat16 g_xb[(size_t)BATCH * FEAT];
__device__ __nv_bfloat16 g_cb[(size_t)NCVS  * FEAT];

// ---------------- K0: convert f32 -> bf16 ----------------
__global__ void split_kernel(const float* __restrict__ X, const float* __restrict__ C) {
    int i  = blockIdx.x * blockDim.x + threadIdx.x;
    int nx = BATCH * FEAT;
    if (i < nx) {
        g_xb[i] = __float2bfloat16(X[i]);
    } else {
        int j = i - nx;
        if (j < NCVS * FEAT) g_cb[j] = __float2bfloat16(C[j]);
    }
}

// ---------------- K1: row squared norms ----------------
__global__ void norms_kernel(const float* __restrict__ X, const float* __restrict__ C) {
    int warp = (blockIdx.x * blockDim.x + threadIdx.x) >> 5;
    int lane = threadIdx.x & 31;
    if (warp < BATCH) {
        const float* r = X + (size_t)warp * FEAT;
        float s = 0.f;
        #pragma unroll
        for (int i = 0; i < 4; i++) { float v = r[lane + 32 * i]; s += v * v; }
        #pragma unroll
        for (int o = 16; o; o >>= 1) s += __shfl_down_sync(0xffffffffu, s, o);
        if (lane == 0) g_xx[warp] = s;
    } else if (warp < BATCH + NCVS) {
        int rr = warp - BATCH;
        const float* r = C + (size_t)rr * FEAT;
        float s = 0.f;
        #pragma unroll
        for (int i = 0; i < 4; i++) { float v = r[lane + 32 * i]; s += v * v; }
        #pragma unroll
        for (int o = 16; o; o >>= 1) s += __shfl_down_sync(0xffffffffu, s, o);
        if (lane == 0) g_cc[rr] = s;
    }
}

// ---------------- K2: bf16 mma.sync distance GEMM ----------------
// smem: 128 rows x 272 B (128 bf16 + 16B pad). Pad makes ldmatrix conflict-free:
// granule (addr>>4)%8 = (r*17 + c16)%8 = (r + c16)%8 -> distinct for 8 rows.
#define SM_STRIDE 272
#define A_OFF 0
#define B_OFF (128 * SM_STRIDE)
#define GEMM_SMEM (2 * 128 * SM_STRIDE)

__device__ __forceinline__ uint32_t smem_u32(const void* p) {
    uint32_t a;
    asm("{ .reg .u64 t; cvta.to.shared.u64 t, %1; cvt.u32.u64 %0, t; }" : "=r"(a) : "l"(p));
    return a;
}
#define LDMX4(r0, r1, r2, r3, addr) \
    asm volatile("ldmatrix.sync.aligned.m8n8.x4.shared.b16 {%0,%1,%2,%3}, [%4];" \
                 : "=r"(r0), "=r"(r1), "=r"(r2), "=r"(r3) : "r"(addr))
#define MMA16816(c, a, b0, b1) \
    asm volatile("mma.sync.aligned.m16n8k16.row.col.f32.bf16.bf16.f32 " \
                 "{%0,%1,%2,%3}, {%4,%5,%6,%7}, {%8,%9}, {%0,%1,%2,%3};" \
                 : "+f"((c)[0]), "+f"((c)[1]), "+f"((c)[2]), "+f"((c)[3]) \
                 : "r"((a)[0]), "r"((a)[1]), "r"((a)[2]), "r"((a)[3]), "r"(b0), "r"(b1))

__global__ __launch_bounds__(256, 2) void gemm_tc_kernel() {
    extern __shared__ char dsm[];
    const int tid  = threadIdx.x;
    const int lane = tid & 31;
    const int w    = tid >> 5;
    const int bm   = blockIdx.y * 128;
    const int bn   = blockIdx.x * 128;
    const int wm   = (w & 3) * 32;   // warp m offset within tile
    const int wn   = (w >> 2) * 64;  // warp n offset within tile

    // fill smem tiles (each thread: 8 x 16B chunks per tile)
    {
        const __nv_bfloat16* Asrc = g_xb + (size_t)bm * FEAT;
        const __nv_bfloat16* Bsrc = g_cb + (size_t)bn * FEAT;
        #pragma unroll
        for (int i = 0; i < 8; i++) {
            int idx = tid + i * 256;          // 0..2047
            int r = idx >> 4, q = idx & 15;
            *(uint4*)(dsm + A_OFF + r * SM_STRIDE + q * 16) =
                *(const uint4*)(Asrc + (size_t)r * FEAT + q * 8);
            *(uint4*)(dsm + B_OFF + r * SM_STRIDE + q * 16) =
                *(const uint4*)(Bsrc + (size_t)r * FEAT + q * 8);
        }
    }
    __syncthreads();

    const uint32_t asb = smem_u32(dsm + A_OFF);
    const uint32_t bsb = smem_u32(dsm + B_OFF);
    const int tile = lane >> 3, rin = lane & 7;

    uint32_t aaddr[2], baddr[4];
    #pragma unroll
    for (int sm = 0; sm < 2; sm++)
        aaddr[sm] = asb + (uint32_t)((wm + sm * 16 + (tile & 1) * 8 + rin) * SM_STRIDE + (tile >> 1) * 16);
    #pragma unroll
    for (int np = 0; np < 4; np++)
        baddr[np] = bsb + (uint32_t)((wn + np * 16 + (tile & 1) * 8 + rin) * SM_STRIDE + (tile >> 1) * 16);

    float acc[2][8][4];
    #pragma unroll
    for (int s = 0; s < 2; s++)
        #pragma unroll
        for (int n = 0; n < 8; n++)
            #pragma unroll
            for (int q = 0; q < 4; q++) acc[s][n][q] = 0.f;

    #pragma unroll
    for (int ks = 0; ks < 8; ks++) {
        uint32_t a[2][4], bfr[4][4];
        LDMX4(a[0][0], a[0][1], a[0][2], a[0][3], aaddr[0] + ks * 32);
        LDMX4(a[1][0], a[1][1], a[1][2], a[1][3], aaddr[1] + ks * 32);
        #pragma unroll
        for (int np = 0; np < 4; np++)
            LDMX4(bfr[np][0], bfr[np][1], bfr[np][2], bfr[np][3], baddr[np] + ks * 32);
        #pragma unroll
        for (int s = 0; s < 2; s++)
            #pragma unroll
            for (int nt = 0; nt < 8; nt++) {
                int np = nt >> 1, odd = nt & 1;
                uint32_t b0 = odd ? bfr[np][1] : bfr[np][0];
                uint32_t b1 = odd ? bfr[np][3] : bfr[np][2];
                MMA16816(acc[s][nt], a[s], b0, b1);
            }
    }

    // epilogue: d2 = xx + cc - 2*dot, clamp >= 0
    const int cb = bn + wn + (lane & 3) * 2;
    #pragma unroll
    for (int s = 0; s < 2; s++) {
        int m0 = bm + wm + s * 16 + (lane >> 2);
        float xx0 = g_xx[m0], xx1 = g_xx[m0 + 8];
        float* row0 = g_d2 + (size_t)m0 * NCVS;
        float* row1 = g_d2 + (size_t)(m0 + 8) * NCVS;
        #pragma unroll
        for (int nt = 0; nt < 8; nt++) {
            int c = cb + nt * 8;
            float2 cc2 = *(const float2*)(g_cc + c);
            float2 o0, o1;
            o0.x = fmaxf(xx0 + cc2.x - 2.0f * acc[s][nt][0], 0.0f);
            o0.y = fmaxf(xx0 + cc2.y - 2.0f * acc[s][nt][1], 0.0f);
            o1.x = fmaxf(xx1 + cc2.x - 2.0f * acc[s][nt][2], 0.0f);
            o1.y = fmaxf(xx1 + cc2.y - 2.0f * acc[s][nt][3], 0.0f);
            *(float2*)(row0 + c) = o0;
            *(float2*)(row1 + c) = o1;
        }
    }
}

// ---------------- K3: topk with exact rescue + fused scatter ----------------
// stage1: per-warp approx top-16; stage2: merge to approx top-24;
// stage3: rescore 24 candidates exactly (f32 dot); stage4: exact top-15.
__global__ void topk_kernel(const float* __restrict__ X, const float* __restrict__ C) {
    __shared__ unsigned s_cb[128];
    __shared__ int      s_cj[128];
    __shared__ int      s_sel[NCAND];
    __shared__ float    s_ed[NCAND];
    __shared__ int      s_knn[KNN];

    const int row  = blockIdx.x;
    const int tid  = threadIdx.x;
    const int lane = tid & 31, w = tid >> 5;
    const float* drow = g_d2 + (size_t)row * NCVS;
    const int wbase = w * 512;

    // stage 1
    unsigned v[16];
    #pragma unroll
    for (int i = 0; i < 16; i++)
        v[i] = __float_as_uint(drow[wbase + i * 32 + lane]);

    unsigned best = 0xFFFFFFFFu; int argj = 0x7FFFFFFF;
    #pragma unroll
    for (int i = 0; i < 16; i++)
        if (v[i] < best) { best = v[i]; argj = wbase + i * 32 + lane; }

    #pragma unroll 1
    for (int it = 0; it < 16; it++) {
        unsigned vmin = __reduce_min_sync(0xffffffffu, best);
        unsigned myj  = (best == vmin) ? (unsigned)argj : 0xFFFFFFFFu;
        unsigned jmin = __reduce_min_sync(0xffffffffu, myj);
        if (lane == 0) { s_cb[w * 16 + it] = vmin; s_cj[w * 16 + it] = (int)jmin; }
        if ((int)(jmin & 31) == lane) {
            int i_sel = (int)((jmin - wbase) >> 5);
            v[i_sel] = 0xFFFFFFFFu;
            best = 0xFFFFFFFFu; argj = 0x7FFFFFFF;
            #pragma unroll
            for (int i = 0; i < 16; i++)
                if (v[i] < best) { best = v[i]; argj = wbase + i * 32 + lane; }
        }
    }
    __syncthreads();

    // stage 2: warp 0 merges 128 -> approx top-24
    if (w == 0) {
        unsigned cbv[4]; int cjv[4];
        #pragma unroll
        for (int q = 0; q < 4; q++) { cbv[q] = s_cb[q * 32 + lane]; cjv[q] = s_cj[q * 32 + lane]; }
        unsigned b2 = 0xFFFFFFFFu; int a2 = 0x7FFFFFFF;
        #pragma unroll
        for (int q = 0; q < 4; q++)
            if (cbv[q] < b2 || (cbv[q] == b2 && cjv[q] < a2)) { b2 = cbv[q]; a2 = cjv[q]; }
        #pragma unroll 1
        for (int it = 0; it < NCAND; it++) {
            unsigned vmin = __reduce_min_sync(0xffffffffu, b2);
            unsigned myj  = (b2 == vmin) ? (unsigned)a2 : 0xFFFFFFFFu;
            unsigned jmin = __reduce_min_sync(0xffffffffu, myj);
            if (lane == 0) s_sel[it] = (int)jmin;
            bool own = false;
            #pragma unroll
            for (int q = 0; q < 4; q++)
                if (cjv[q] == (int)jmin && cbv[q] == vmin) { cbv[q] = 0xFFFFFFFFu; own = true; }
            if (own) {
                b2 = 0xFFFFFFFFu; a2 = 0x7FFFFFFF;
                #pragma unroll
                for (int q = 0; q < 4; q++)
                    if (cbv[q] < b2 || (cbv[q] == b2 && cjv[q] < a2)) { b2 = cbv[q]; a2 = cjv[q]; }
            }
        }
    }
    __syncthreads();

    // stage 3: exact f32 rescoring of 24 candidates (3 per warp)
    {
        float4 xq = *(const float4*)(X + (size_t)row * FEAT + lane * 4);
        float xxv = g_xx[row];
        #pragma unroll
        for (int c = w; c < NCAND; c += 8) {
            int j = s_sel[c];
            float4 cq = *(const float4*)(C + (size_t)j * FEAT + lane * 4);
            float p = xq.x * cq.x + xq.y * cq.y + xq.z * cq.z + xq.w * cq.w;
            #pragma unroll
            for (int o = 16; o; o >>= 1) p += __shfl_down_sync(0xffffffffu, p, o);
            if (lane == 0) s_ed[c] = fmaxf(xxv + g_cc[j] - 2.0f * p, 0.0f);
        }
    }
    __syncthreads();

    // stage 4: exact top-15 of 24 + scatter
    if (w == 0) {
        unsigned val = (lane < NCAND) ? __float_as_uint(s_ed[lane]) : 0xFFFFFFFFu;
        int      jv  = (lane < NCAND) ? s_sel[lane] : 0x7FFFFFFF;
        #pragma unroll 1
        for (int it = 0; it < KNN; it++) {
            unsigned vmin = __reduce_min_sync(0xffffffffu, val);
            unsigned myj  = (val == vmin) ? (unsigned)jv : 0xFFFFFFFFu;
            unsigned jmin = __reduce_min_sync(0xffffffffu, myj);
            if (lane == 0) { s_knn[it] = (int)jmin; g_knn[row * KNN + it] = (int)jmin; }
            if (jv == (int)jmin && val == vmin) val = 0xFFFFFFFFu;
        }
        __syncwarp();
        int closest = s_knn[0];
        if (lane == 0) atomicAdd(&g_visits[closest], 1);
        if (lane < KNN) atomicAdd(&g_cce[(size_t)closest * NCVS + s_knn[lane]], 1);
    }
}

// ---------------- K4: build per-label neighbor lists (vectorized) ----------------
// (0.9f)^10 < f32(double(0.9^10)) so integer-edge rows keep enc <= 9 only.
__global__ void build_kernel(const float* __restrict__ edges, const float* __restrict__ conn) {
    __shared__ int s_scan[256];
    const int lab = blockIdx.x;
    const int tid = threadIdx.x;
    float vis = (float)g_visits[lab];
    const int4*   ccer = (const int4*)  (g_cce + (size_t)lab * NCVS);
    const float4* er   = (const float4*)(edges + (size_t)lab * NCVS);
    const float4* cor  = (const float4*)(conn  + (size_t)lab * NCVS);

    unsigned mask = 0;
    #pragma unroll
    for (int it = 0; it < 4; it++) {
        int g = tid + (it << 8);
        int4   c4 = ccer[g];
        float4 e4 = er[g];
        float4 o4 = cor[g];
        int    cc[4] = {c4.x, c4.y, c4.z, c4.w};
        float  ee[4] = {e4.x, e4.y, e4.z, e4.w};
        float  oo[4] = {o4.x, o4.y, o4.z, o4.w};
        #pragma unroll
        for (int q = 0; q < 4; q++) {
            bool keep = false;
            if (cc[q] > 0 || ee[q] > 0.f) {
                float base = fmaxf(ee[q], (cc[q] > 0) ? 1.0f : 0.0f);
                float enc  = fmaxf(vis - (float)cc[q], 0.0f);
                if (base >= 1.0f) keep = (enc < 9.5f);
                else {
                    float en = base * __powf(0.89999997615814209f, enc);
                    keep = !(en < 0.34867844358f);
                }
                keep = keep && (oo[q] < 1.0f);
            }
            if (keep) mask |= (1u << (it * 4 + q));
        }
    }
    int cnt = __popc(mask);
    s_scan[tid] = cnt;
    __syncthreads();
    for (int off = 1; off < 256; off <<= 1) {
        int vv = (tid >= off) ? s_scan[tid - off] : 0;
        __syncthreads();
        s_scan[tid] += vv;
        __syncthreads();
    }
    int pos = s_scan[tid] - cnt;
    int* dst = g_nlist + (size_t)lab * NCVS;
    #pragma unroll
    for (int b = 0; b < 16; b++)
        if (mask & (1u << b)) dst[pos++] = 4 * (tid + ((b >> 2) << 8)) + (b & 3);
    if (tid == 255) g_ncnt[lab] = s_scan[255];
}

// ---------------- K5: per-sample loss, exact f32 neighbor distances ----------------
__global__ void loss_kernel(const float* __restrict__ X, const float* __restrict__ C,
                            const int* __restrict__ labels) {
    __shared__ float s_dp[4], s_se[4], s_sed[4];
    const int b    = blockIdx.x;
    const int tid  = threadIdx.x;
    const int lane = tid & 31, wid = tid >> 5;
    const int lab  = labels[b];

    const float* xr = X + (size_t)b   * FEAT;
    const float* cr = C + (size_t)lab * FEAT;
    float dlt = xr[tid] - cr[tid];
    float dp  = dlt * dlt;
    #pragma unroll
    for (int o = 16; o; o >>= 1) dp += __shfl_down_sync(0xffffffffu, dp, o);

    const int  L  = g_ncnt[lab];
    const int* nl = g_nlist + (size_t)lab * NCVS;
    const float xxv = g_xx[b];
    float4 xq = *(const float4*)(xr + lane * 4);

    float se = 0.f, sed = 0.f;
    for (int k = wid; k < L; k += 4) {
        int j = nl[k];
        float4 cq = *(const float4*)(C + (size_t)j * FEAT + lane * 4);
        float p = xq.x * cq.x + xq.y * cq.y + xq.z * cq.z + xq.w * cq.w;
        #pragma unroll
        for (int o = 16; o; o >>= 1) p += __shfl_down_sync(0xffffffffu, p, o);
        if (lane == 0) {
            float dd = fmaxf(xxv + g_cc[j] - 2.0f * p, 0.0f);
            if (dd > 0.f) {
                float ex = expf(-0.001f * dd);
                se  += ex;
                sed += ex * dd;
            }
        }
    }

    if (lane == 0) { s_dp[wid] = dp; s_se[wid] = se; s_sed[wid] = sed; }
    __syncthreads();
    if (tid == 0) {
        float dpt  = s_dp[0]  + s_dp[1]  + s_dp[2]  + s_dp[3];
        float set  = s_se[0]  + s_se[1]  + s_se[2]  + s_se[3];
        float sedt = s_sed[0] + s_sed[1] + s_sed[2] + s_sed[3];
        float wsum = (set > 0.f) ? (sedt / set) : 0.f;   // nan -> 0 branch
        float mu = dpt - wsum;
        if (mu > 0.f) atomicAdd(&g_loss, (double)mu);
    }
}

// ---------------- K6: finalize ----------------
__global__ void finalize_kernel(float* out) {
    if (threadIdx.x == 0) out[0] = (float)(g_loss * (1.0 / (double)BATCH));
}

// ---------------- K7: undo scatter (self-cleaning state) ----------------
__global__ void undo_kernel() {
    int b = blockIdx.x * blockDim.x + threadIdx.x;
    if (b == 0) g_loss = 0.0;
    if (b >= BATCH) return;
    int closest = g_knn[b * KNN];
    atomicSub(&g_visits[closest], 1);
    #pragma unroll
    for (int k = 0; k < KNN; k++)
        atomicSub(&g_cce[(size_t)closest * NCVS + g_knn[b * KNN + k]], 1);
}

// ---------------- launch ----------------
extern "C" void kernel_launch(void* const* d_in, const int* in_sizes, int n_in,
                              void* d_out, int out_size) {
    const float* x      = (const float*)d_in[0];
    const float* cvs    = (const float*)d_in[1];
    const float* edges  = (const float*)d_in[2];
    const float* conn   = (const float*)d_in[3];
    const int*   labels = (const int*)d_in[4];
    float* out = (float*)d_out;

    cudaFuncSetAttribute(gemm_tc_kernel, cudaFuncAttributeMaxDynamicSharedMemorySize, GEMM_SMEM);

    split_kernel<<<(BATCH + NCVS) * FEAT / 256, 256>>>(x, cvs);
    norms_kernel<<<(BATCH + NCVS) / 8, 256>>>(x, cvs);
    gemm_tc_kernel<<<dim3(NCVS / 128, BATCH / 128), 256, GEMM_SMEM>>>();
    topk_kernel<<<BATCH, 256>>>(x, cvs);
    build_kernel<<<NCVS, 256>>>(edges, conn);
    loss_kernel<<<BATCH, 128>>>(x, cvs, labels);
    finalize_kernel<<<1, 32>>>(out);
    undo_kernel<<<BATCH / 256, 256>>>();
}

// round 7
// speedup vs baseline: 1.9869x; 1.2114x over previous
#include <cuda_runtime.h>
#include <cuda_bf16.h>
#include <cstdint>
#include <math.h>

#define BATCH 8192
#define NCVS  4096
#define FEAT  128
#define KNN   15
#define CMAX  512   // candidate buffer (typical occupancy ~30)

// ---------------- static scratch ----------------
__device__ float  g_d2[(size_t)BATCH * NCVS];    // approx (bf16-GEMM) distances, f32
__device__ int    g_cce[(size_t)NCVS * NCVS];    // self-cleaning via undo
__device__ int    g_nlist[(size_t)NCVS * NCVS];  // per-label neighbor lists
__device__ int    g_ncnt[NCVS];
__device__ int    g_visits[NCVS];                // self-cleaning
__device__ int    g_knn[BATCH * KNN];
__device__ float  g_xx[BATCH];
__device__ float  g_cc[NCVS];
__device__ double g_loss;                        // self-cleaning
__device__ __nv_bfloat16 g_xb[(size_t)BATCH * FEAT];
__device__ __nv_bfloat16 g_cb[(size_t)NCVS  * FEAT];

// ---------------- K0: convert f32 -> bf16 ----------------
__global__ void split_kernel(const float* __restrict__ X, const float* __restrict__ C) {
    int i  = blockIdx.x * blockDim.x + threadIdx.x;
    int nx = BATCH * FEAT;
    if (i < nx) {
        g_xb[i] = __float2bfloat16(X[i]);
    } else {
        int j = i - nx;
        if (j < NCVS * FEAT) g_cb[j] = __float2bfloat16(C[j]);
    }
}

// ---------------- K1: row squared norms ----------------
__global__ void norms_kernel(const float* __restrict__ X, const float* __restrict__ C) {
    int warp = (blockIdx.x * blockDim.x + threadIdx.x) >> 5;
    int lane = threadIdx.x & 31;
    if (warp < BATCH) {
        const float* r = X + (size_t)warp * FEAT;
        float s = 0.f;
        #pragma unroll
        for (int i = 0; i < 4; i++) { float v = r[lane + 32 * i]; s += v * v; }
        #pragma unroll
        for (int o = 16; o; o >>= 1) s += __shfl_down_sync(0xffffffffu, s, o);
        if (lane == 0) g_xx[warp] = s;
    } else if (warp < BATCH + NCVS) {
        int rr = warp - BATCH;
        const float* r = C + (size_t)rr * FEAT;
        float s = 0.f;
        #pragma unroll
        for (int i = 0; i < 4; i++) { float v = r[lane + 32 * i]; s += v * v; }
        #pragma unroll
        for (int o = 16; o; o >>= 1) s += __shfl_down_sync(0xffffffffu, s, o);
        if (lane == 0) g_cc[rr] = s;
    }
}

// ---------------- K2: bf16 mma.sync distance GEMM ----------------
#define SM_STRIDE 272
#define A_OFF 0
#define B_OFF (128 * SM_STRIDE)
#define GEMM_SMEM (2 * 128 * SM_STRIDE)

__device__ __forceinline__ uint32_t smem_u32(const void* p) {
    uint32_t a;
    asm("{ .reg .u64 t; cvta.to.shared.u64 t, %1; cvt.u32.u64 %0, t; }" : "=r"(a) : "l"(p));
    return a;
}
#define LDMX4(r0, r1, r2, r3, addr) \
    asm volatile("ldmatrix.sync.aligned.m8n8.x4.shared.b16 {%0,%1,%2,%3}, [%4];" \
                 : "=r"(r0), "=r"(r1), "=r"(r2), "=r"(r3) : "r"(addr))
#define MMA16816(c, a, b0, b1) \
    asm volatile("mma.sync.aligned.m16n8k16.row.col.f32.bf16.bf16.f32 " \
                 "{%0,%1,%2,%3}, {%4,%5,%6,%7}, {%8,%9}, {%0,%1,%2,%3};" \
                 : "+f"((c)[0]), "+f"((c)[1]), "+f"((c)[2]), "+f"((c)[3]) \
                 : "r"((a)[0]), "r"((a)[1]), "r"((a)[2]), "r"((a)[3]), "r"(b0), "r"(b1))

__global__ __launch_bounds__(256, 2) void gemm_tc_kernel() {
    extern __shared__ char dsm[];
    const int tid  = threadIdx.x;
    const int lane = tid & 31;
    const int w    = tid >> 5;
    const int bm   = blockIdx.y * 128;
    const int bn   = blockIdx.x * 128;
    const int wm   = (w & 3) * 32;
    const int wn   = (w >> 2) * 64;

    {
        const __nv_bfloat16* Asrc = g_xb + (size_t)bm * FEAT;
        const __nv_bfloat16* Bsrc = g_cb + (size_t)bn * FEAT;
        #pragma unroll
        for (int i = 0; i < 8; i++) {
            int idx = tid + i * 256;
            int r = idx >> 4, q = idx & 15;
            *(uint4*)(dsm + A_OFF + r * SM_STRIDE + q * 16) =
                *(const uint4*)(Asrc + (size_t)r * FEAT + q * 8);
            *(uint4*)(dsm + B_OFF + r * SM_STRIDE + q * 16) =
                *(const uint4*)(Bsrc + (size_t)r * FEAT + q * 8);
        }
    }
    __syncthreads();

    const uint32_t asb = smem_u32(dsm + A_OFF);
    const uint32_t bsb = smem_u32(dsm + B_OFF);
    const int tile = lane >> 3, rin = lane & 7;

    uint32_t aaddr[2], baddr[4];
    #pragma unroll
    for (int sm = 0; sm < 2; sm++)
        aaddr[sm] = asb + (uint32_t)((wm + sm * 16 + (tile & 1) * 8 + rin) * SM_STRIDE + (tile >> 1) * 16);
    #pragma unroll
    for (int np = 0; np < 4; np++)
        baddr[np] = bsb + (uint32_t)((wn + np * 16 + (tile & 1) * 8 + rin) * SM_STRIDE + (tile >> 1) * 16);

    float acc[2][8][4];
    #pragma unroll
    for (int s = 0; s < 2; s++)
        #pragma unroll
        for (int n = 0; n < 8; n++)
            #pragma unroll
            for (int q = 0; q < 4; q++) acc[s][n][q] = 0.f;

    #pragma unroll
    for (int ks = 0; ks < 8; ks++) {
        uint32_t a[2][4], bfr[4][4];
        LDMX4(a[0][0], a[0][1], a[0][2], a[0][3], aaddr[0] + ks * 32);
        LDMX4(a[1][0], a[1][1], a[1][2], a[1][3], aaddr[1] + ks * 32);
        #pragma unroll
        for (int np = 0; np < 4; np++)
            LDMX4(bfr[np][0], bfr[np][1], bfr[np][2], bfr[np][3], baddr[np] + ks * 32);
        #pragma unroll
        for (int s = 0; s < 2; s++)
            #pragma unroll
            for (int nt = 0; nt < 8; nt++) {
                int np = nt >> 1, odd = nt & 1;
                uint32_t b0 = odd ? bfr[np][1] : bfr[np][0];
                uint32_t b1 = odd ? bfr[np][3] : bfr[np][2];
                MMA16816(acc[s][nt], a[s], b0, b1);
            }
    }

    const int cb = bn + wn + (lane & 3) * 2;
    #pragma unroll
    for (int s = 0; s < 2; s++) {
        int m0 = bm + wm + s * 16 + (lane >> 2);
        float xx0 = g_xx[m0], xx1 = g_xx[m0 + 8];
        float* row0 = g_d2 + (size_t)m0 * NCVS;
        float* row1 = g_d2 + (size_t)(m0 + 8) * NCVS;
        #pragma unroll
        for (int nt = 0; nt < 8; nt++) {
            int c = cb + nt * 8;
            float2 cc2 = *(const float2*)(g_cc + c);
            float2 o0, o1;
            o0.x = fmaxf(xx0 + cc2.x - 2.0f * acc[s][nt][0], 0.0f);
            o0.y = fmaxf(xx0 + cc2.y - 2.0f * acc[s][nt][1], 0.0f);
            o1.x = fmaxf(xx1 + cc2.x - 2.0f * acc[s][nt][2], 0.0f);
            o1.y = fmaxf(xx1 + cc2.y - 2.0f * acc[s][nt][3], 0.0f);
            *(float2*)(row0 + c) = o0;
            *(float2*)(row1 + c) = o1;
        }
    }
}

// ---------------- K3: threshold-filter topk + exact rescore + fused scatter ----------
// Candidates = {j : approx_j < m + d + 1.0} where count(approx < m+d) >= 15.
// Containment: exact_j <= exact15 <= approx15 + err <= m+d+err  =>  approx_j <=
// exact_j + err < m+d+1.0 for err <= 0.5 (bf16 GEMM abs error ~0.15). The
// candidate SET is order-independent; exact rescore + lex-min selection gives
// the reference-identical knn (ties -> lowest index).
__global__ void topk_kernel(const float* __restrict__ X, const float* __restrict__ C) {
    __shared__ float s_red[8];
    __shared__ int   s_icnt[8];
    __shared__ int   s_cnt;
    __shared__ int   s_cand[CMAX];
    __shared__ float s_ed[CMAX];
    __shared__ int   s_knn[KNN];

    const int row  = blockIdx.x;
    const int tid  = threadIdx.x;
    const int lane = tid & 31, w = tid >> 5;
    const float* drow = g_d2 + (size_t)row * NCVS;
    const int wbase = w * 512;

    // load 16 values per thread (register-resident for count passes)
    float v[16];
    #pragma unroll
    for (int i = 0; i < 16; i++) v[i] = drow[wbase + i * 32 + lane];

    // block min
    float mn = v[0];
    #pragma unroll
    for (int i = 1; i < 16; i++) mn = fminf(mn, v[i]);
    #pragma unroll
    for (int o = 16; o; o >>= 1) mn = fminf(mn, __shfl_xor_sync(0xffffffffu, mn, o));
    if (lane == 0) s_red[w] = mn;
    if (tid == 0) s_cnt = 0;
    __syncthreads();
    float m = s_red[0];
    #pragma unroll
    for (int q = 1; q < 8; q++) m = fminf(m, s_red[q]);

    // doubling threshold search: smallest d in {2,4,8,...} with count >= KNN
    float d = 2.0f;
    for (int iter = 0; iter < 24; iter++) {
        float T0 = m + d;
        unsigned c = 0;
        #pragma unroll
        for (int i = 0; i < 16; i++) c += (v[i] < T0) ? 1u : 0u;
        c = __reduce_add_sync(0xffffffffu, c);
        if (lane == 0) s_icnt[w] = (int)c;
        __syncthreads();
        int total = s_icnt[0] + s_icnt[1] + s_icnt[2] + s_icnt[3]
                  + s_icnt[4] + s_icnt[5] + s_icnt[6] + s_icnt[7];
        if (total >= KNN) break;
        d *= 2.0f;
        __syncthreads();
    }
    const float T = m + d + 1.0f;

    // compact candidate indices (set; order irrelevant)
    #pragma unroll
    for (int i = 0; i < 16; i++) {
        if (v[i] < T) {
            int p = atomicAdd(&s_cnt, 1);
            if (p < CMAX) s_cand[p] = wbase + i * 32 + lane;
        }
    }
    __syncthreads();
    const int M = (s_cnt < CMAX) ? s_cnt : CMAX;

    // exact f32 rescore of candidates
    {
        float4 xq = *(const float4*)(X + (size_t)row * FEAT + lane * 4);
        float xxv = g_xx[row];
        for (int c = w; c < M; c += 8) {
            int j = s_cand[c];
            float4 cq = *(const float4*)(C + (size_t)j * FEAT + lane * 4);
            float p = xq.x * cq.x + xq.y * cq.y + xq.z * cq.z + xq.w * cq.w;
            #pragma unroll
            for (int o = 16; o; o >>= 1) p += __shfl_down_sync(0xffffffffu, p, o);
            if (lane == 0) s_ed[c] = fmaxf(xxv + g_cc[j] - 2.0f * p, 0.0f);
        }
    }
    __syncthreads();

    // exact top-15 of M candidates (warp 0), lex-min (value, index)
    if (w == 0) {
        const int S = (M + 31) >> 5;     // slots per lane (typically 1-2)
        unsigned sv[16]; int sj[16];
        for (int q = 0; q < S; q++) {
            int idx = q * 32 + lane;
            sv[q] = (idx < M) ? __float_as_uint(s_ed[idx]) : 0xFFFFFFFFu;
            sj[q] = (idx < M) ? s_cand[idx] : 0x7FFFFFFF;
        }
        #pragma unroll 1
        for (int it = 0; it < KNN; it++) {
            unsigned lb = 0xFFFFFFFFu; int lj = 0x7FFFFFFF;
            for (int q = 0; q < S; q++)
                if (sv[q] < lb || (sv[q] == lb && sj[q] < lj)) { lb = sv[q]; lj = sj[q]; }
            unsigned vmin = __reduce_min_sync(0xffffffffu, lb);
            unsigned myj  = (lb == vmin) ? (unsigned)lj : 0xFFFFFFFFu;
            unsigned jmin = __reduce_min_sync(0xffffffffu, myj);
            if (lane == 0) { s_knn[it] = (int)jmin; g_knn[row * KNN + it] = (int)jmin; }
            for (int q = 0; q < S; q++)
                if (sj[q] == (int)jmin && sv[q] == vmin) sv[q] = 0xFFFFFFFFu;
        }
        __syncwarp();
        int closest = s_knn[0];
        if (lane == 0) atomicAdd(&g_visits[closest], 1);
        if (lane < KNN) atomicAdd(&g_cce[(size_t)closest * NCVS + s_knn[lane]], 1);
    }
}

// ---------------- K4: build per-label neighbor lists (vectorized) ----------------
// (0.9f)^10 < f32(double(0.9^10)) so integer-edge rows keep enc <= 9 only.
__global__ void build_kernel(const float* __restrict__ edges, const float* __restrict__ conn) {
    __shared__ int s_scan[256];
    const int lab = blockIdx.x;
    const int tid = threadIdx.x;
    float vis = (float)g_visits[lab];
    const int4*   ccer = (const int4*)  (g_cce + (size_t)lab * NCVS);
    const float4* er   = (const float4*)(edges + (size_t)lab * NCVS);
    const float4* cor  = (const float4*)(conn  + (size_t)lab * NCVS);

    unsigned mask = 0;
    #pragma unroll
    for (int it = 0; it < 4; it++) {
        int g = tid + (it << 8);
        int4   c4 = ccer[g];
        float4 e4 = er[g];
        float4 o4 = cor[g];
        int    cc[4] = {c4.x, c4.y, c4.z, c4.w};
        float  ee[4] = {e4.x, e4.y, e4.z, e4.w};
        float  oo[4] = {o4.x, o4.y, o4.z, o4.w};
        #pragma unroll
        for (int q = 0; q < 4; q++) {
            bool keep = false;
            if (cc[q] > 0 || ee[q] > 0.f) {
                float base = fmaxf(ee[q], (cc[q] > 0) ? 1.0f : 0.0f);
                float enc  = fmaxf(vis - (float)cc[q], 0.0f);
                if (base >= 1.0f) keep = (enc < 9.5f);
                else {
                    float en = base * __powf(0.89999997615814209f, enc);
                    keep = !(en < 0.34867844358f);
                }
                keep = keep && (oo[q] < 1.0f);
            }
            if (keep) mask |= (1u << (it * 4 + q));
        }
    }
    int cnt = __popc(mask);
    s_scan[tid] = cnt;
    __syncthreads();
    for (int off = 1; off < 256; off <<= 1) {
        int vv = (tid >= off) ? s_scan[tid - off] : 0;
        __syncthreads();
        s_scan[tid] += vv;
        __syncthreads();
    }
    int pos = s_scan[tid] - cnt;
    int* dst = g_nlist + (size_t)lab * NCVS;
    #pragma unroll
    for (int b = 0; b < 16; b++)
        if (mask & (1u << b)) dst[pos++] = 4 * (tid + ((b >> 2) << 8)) + (b & 3);
    if (tid == 255) g_ncnt[lab] = s_scan[255];
}

// ---------------- K5: per-sample loss, exact f32 neighbor distances ----------------
__global__ void loss_kernel(const float* __restrict__ X, const float* __restrict__ C,
                            const int* __restrict__ labels) {
    __shared__ float s_dp[4], s_se[4], s_sed[4];
    const int b    = blockIdx.x;
    const int tid  = threadIdx.x;
    const int lane = tid & 31, wid = tid >> 5;
    const int lab  = labels[b];

    const float* xr = X + (size_t)b   * FEAT;
    const float* cr = C + (size_t)lab * FEAT;
    float dlt = xr[tid] - cr[tid];
    float dp  = dlt * dlt;
    #pragma unroll
    for (int o = 16; o; o >>= 1) dp += __shfl_down_sync(0xffffffffu, dp, o);

    const int  L  = g_ncnt[lab];
    const int* nl = g_nlist + (size_t)lab * NCVS;
    const float xxv = g_xx[b];
    float4 xq = *(const float4*)(xr + lane * 4);

    float se = 0.f, sed = 0.f;
    for (int k = wid; k < L; k += 4) {
        int j = nl[k];
        float4 cq = *(const float4*)(C + (size_t)j * FEAT + lane * 4);
        float p = xq.x * cq.x + xq.y * cq.y + xq.z * cq.z + xq.w * cq.w;
        #pragma unroll
        for (int o = 16; o; o >>= 1) p += __shfl_down_sync(0xffffffffu, p, o);
        if (lane == 0) {
            float dd = fmaxf(xxv + g_cc[j] - 2.0f * p, 0.0f);
            if (dd > 0.f) {
                float ex = expf(-0.001f * dd);
                se  += ex;
                sed += ex * dd;
            }
        }
    }

    if (lane == 0) { s_dp[wid] = dp; s_se[wid] = se; s_sed[wid] = sed; }
    __syncthreads();
    if (tid == 0) {
        float dpt  = s_dp[0]  + s_dp[1]  + s_dp[2]  + s_dp[3];
        float set  = s_se[0]  + s_se[1]  + s_se[2]  + s_se[3];
        float sedt = s_sed[0] + s_sed[1] + s_sed[2] + s_sed[3];
        float wsum = (set > 0.f) ? (sedt / set) : 0.f;   // nan -> 0 branch
        float mu = dpt - wsum;
        if (mu > 0.f) atomicAdd(&g_loss, (double)mu);
    }
}

// ---------------- K6: finalize ----------------
__global__ void finalize_kernel(float* out) {
    if (threadIdx.x == 0) out[0] = (float)(g_loss * (1.0 / (double)BATCH));
}

// ---------------- K7: undo scatter (self-cleaning state) ----------------
__global__ void undo_kernel() {
    int b = blockIdx.x * blockDim.x + threadIdx.x;
    if (b == 0) g_loss = 0.0;
    if (b >= BATCH) return;
    int closest = g_knn[b * KNN];
    atomicSub(&g_visits[closest], 1);
    #pragma unroll
    for (int k = 0; k < KNN; k++)
        atomicSub(&g_cce[(size_t)closest * NCVS + g_knn[b * KNN + k]], 1);
}

// ---------------- launch ----------------
extern "C" void kernel_launch(void* const* d_in, const int* in_sizes, int n_in,
                              void* d_out, int out_size) {
    const float* x      = (const float*)d_in[0];
    const float* cvs    = (const float*)d_in[1];
    const float* edges  = (const float*)d_in[2];
    const float* conn   = (const float*)d_in[3];
    const int*   labels = (const int*)d_in[4];
    float* out = (float*)d_out;

    cudaFuncSetAttribute(gemm_tc_kernel, cudaFuncAttributeMaxDynamicSharedMemorySize, GEMM_SMEM);

    split_kernel<<<(BATCH + NCVS) * FEAT / 256, 256>>>(x, cvs);
    norms_kernel<<<(BATCH + NCVS) / 8, 256>>>(x, cvs);
    gemm_tc_kernel<<<dim3(NCVS / 128, BATCH / 128), 256, GEMM_SMEM>>>();
    topk_kernel<<<BATCH, 256>>>(x, cvs);
    build_kernel<<<NCVS, 256>>>(edges, conn);
    loss_kernel<<<BATCH, 128>>>(x, cvs, labels);
    finalize_kernel<<<1, 32>>>(out);
    undo_kernel<<<BATCH / 256, 256>>>();
}